// round 13
// baseline (speedup 1.0000x reference)
#include <cuda_runtime.h>
#include <cuda_bf16.h>
#include <cstdint>

// RNNModel: T=512, B=256, I=256, H=512, fp32.
//   K1: xp = x @ w_ih^T + (b_ih + b_hh)      -> mma.sync 3xTF32 GEMM (2 CTA/SM)
//   K2: h_t = tanh(xp_t + h_{t-1} @ w_hh^T)  -> persistent; warps split N (no reduce), b-major hT
//   K3: out = hs @ w_fc^T + b_fc             -> mma.sync 3xTF32 GEMM

#define T_ 512
#define B_ 256
#define I_ 256
#define H_ 512

#define NG  16
#define NSL 8
#define BT  16
#define NS  64
#define WPAD 68
#define HSTR 516   // b-major hT row stride (floats); 516*4 % 16 == 0, bank-spread

__device__ float g_xp[(size_t)T_ * B_ * H_];
__device__ float g_hs[(size_t)T_ * B_ * H_];
__device__ int   g_cnt[NG];

// ---------------- helpers ----------------
__device__ __forceinline__ unsigned long long f32x2_fma(unsigned long long a,
                                                        unsigned long long b,
                                                        unsigned long long c) {
    unsigned long long d;
    asm("fma.rn.f32x2 %0, %1, %2, %3;" : "=l"(d) : "l"(a), "l"(b), "l"(c));
    return d;
}
__device__ __forceinline__ unsigned long long f32x2_splat(float x) {
    unsigned long long d;
    unsigned int xi = __float_as_uint(x);
    asm("mov.b64 %0, {%1, %1};" : "=l"(d) : "r"(xi));
    return d;
}
__device__ __forceinline__ float2 f32x2_unpack(unsigned long long v) {
    unsigned int lo, hi;
    asm("mov.b64 {%0, %1}, %2;" : "=r"(lo), "=r"(hi) : "l"(v));
    float2 r;
    r.x = __uint_as_float(lo);
    r.y = __uint_as_float(hi);
    return r;
}
__device__ __forceinline__ uint32_t smem_u32(const void* p) {
    uint32_t a;
    asm("{ .reg .u64 t; cvta.to.shared.u64 t, %1; cvt.u32.u64 %0, t; }" : "=r"(a) : "l"(p));
    return a;
}
__device__ __forceinline__ void cp_async16(uint32_t saddr, const void* gptr) {
    asm volatile("cp.async.ca.shared.global [%0], [%1], 16;" :: "r"(saddr), "l"(gptr));
}
#define CP_COMMIT_WAIT() \
    asm volatile("cp.async.commit_group;\n\tcp.async.wait_group 0;" ::: "memory")

// ---------------- tf32 helpers ----------------
__device__ __forceinline__ uint32_t cvt_tf32(float x) {
    uint32_t r;
    asm("cvt.rna.tf32.f32 %0, %1;" : "=r"(r) : "f"(x));
    return r;
}
__device__ __forceinline__ void split_tf32(float x, float& big, float& small) {
    big = __uint_as_float(cvt_tf32(x));
    small = __uint_as_float(cvt_tf32(x - big));
}
__device__ __forceinline__ void mma16n8k8(float* c, const uint32_t* a, const uint32_t* b) {
    asm volatile("mma.sync.aligned.m16n8k8.row.col.f32.tf32.tf32.f32 "
        "{%0,%1,%2,%3}, {%4,%5,%6,%7}, {%8,%9}, {%0,%1,%2,%3};"
        : "+f"(c[0]), "+f"(c[1]), "+f"(c[2]), "+f"(c[3])
        : "r"(a[0]), "r"(a[1]), "r"(a[2]), "r"(a[3]), "r"(b[0]), "r"(b[1]));
}

// ---------------- K1/K3: 3xTF32 mma.sync GEMM (now 2 CTA/SM) ----------------
#define KCHUNK 16
#define PADS 20
#define ARRF (128 * PADS)
#define STGF (4 * ARRF)
#define GEMM_SMEM_BYTES (2 * STGF * 4)   // 81920

__global__ void __launch_bounds__(256, 2) mma_gemm_kernel(
    const float* __restrict__ A, const float* __restrict__ Bm,
    const float* __restrict__ b1, const float* __restrict__ b2,
    float* __restrict__ C, int M, int N, int K)
{
    extern __shared__ float sh[];
    const int tid = threadIdx.x;
    const int m0 = blockIdx.y << 7;
    const int n0 = blockIdx.x << 7;
    const int lane = tid & 31, wid = tid >> 5;
    const int gid = lane >> 2, tig = lane & 3;
    const int wm = wid >> 1, wn = wid & 1;

    const int lrow = tid >> 1;
    const int lko  = (tid & 1) << 3;

    const float* Ap = A + (size_t)(m0 + lrow) * K + lko;
    const float* Bp = Bm + (size_t)(n0 + lrow) * K + lko;

    float acc[2][8][4];
#pragma unroll
    for (int mt = 0; mt < 2; mt++)
#pragma unroll
        for (int nt = 0; nt < 8; nt++)
#pragma unroll
            for (int i = 0; i < 4; i++) acc[mt][nt][i] = 0.0f;

    const int NC = K >> 4;

    float4 ar0 = *(const float4*)(Ap);
    float4 ar1 = *(const float4*)(Ap + 4);
    float4 br0 = *(const float4*)(Bp);
    float4 br1 = *(const float4*)(Bp + 4);

    for (int kc = 0; kc < NC; kc++) {
        const int s = kc & 1;
        float* AB = sh + s * STGF;
        float* AS = AB + ARRF;
        float* BB = AS + ARRF;
        float* BS = BB + ARRF;

        {
            float4 bg, sm;
            const int sa = lrow * PADS + lko;
            split_tf32(ar0.x, bg.x, sm.x); split_tf32(ar0.y, bg.y, sm.y);
            split_tf32(ar0.z, bg.z, sm.z); split_tf32(ar0.w, bg.w, sm.w);
            *(float4*)(AB + sa) = bg; *(float4*)(AS + sa) = sm;
            split_tf32(ar1.x, bg.x, sm.x); split_tf32(ar1.y, bg.y, sm.y);
            split_tf32(ar1.z, bg.z, sm.z); split_tf32(ar1.w, bg.w, sm.w);
            *(float4*)(AB + sa + 4) = bg; *(float4*)(AS + sa + 4) = sm;
            split_tf32(br0.x, bg.x, sm.x); split_tf32(br0.y, bg.y, sm.y);
            split_tf32(br0.z, bg.z, sm.z); split_tf32(br0.w, bg.w, sm.w);
            *(float4*)(BB + sa) = bg; *(float4*)(BS + sa) = sm;
            split_tf32(br1.x, bg.x, sm.x); split_tf32(br1.y, bg.y, sm.y);
            split_tf32(br1.z, bg.z, sm.z); split_tf32(br1.w, bg.w, sm.w);
            *(float4*)(BB + sa + 4) = bg; *(float4*)(BS + sa + 4) = sm;
        }
        __syncthreads();

        if (kc + 1 < NC) {
            const int K0 = (kc + 1) << 4;
            ar0 = *(const float4*)(Ap + K0);
            ar1 = *(const float4*)(Ap + K0 + 4);
            br0 = *(const float4*)(Bp + K0);
            br1 = *(const float4*)(Bp + K0 + 4);
        }

#pragma unroll
        for (int lk8 = 0; lk8 < KCHUNK; lk8 += 8) {
            uint32_t ab[2][4], as_[2][4], bb[8][2], bs[8][2];
#pragma unroll
            for (int mt = 0; mt < 2; mt++) {
                const int r = (wm << 5) + (mt << 4) + gid;
                ab[mt][0]  = __float_as_uint(AB[r * PADS + lk8 + tig]);
                ab[mt][1]  = __float_as_uint(AB[(r + 8) * PADS + lk8 + tig]);
                ab[mt][2]  = __float_as_uint(AB[r * PADS + lk8 + tig + 4]);
                ab[mt][3]  = __float_as_uint(AB[(r + 8) * PADS + lk8 + tig + 4]);
                as_[mt][0] = __float_as_uint(AS[r * PADS + lk8 + tig]);
                as_[mt][1] = __float_as_uint(AS[(r + 8) * PADS + lk8 + tig]);
                as_[mt][2] = __float_as_uint(AS[r * PADS + lk8 + tig + 4]);
                as_[mt][3] = __float_as_uint(AS[(r + 8) * PADS + lk8 + tig + 4]);
            }
#pragma unroll
            for (int nt = 0; nt < 8; nt++) {
                const int nn = (wn << 6) + (nt << 3) + gid;
                bb[nt][0] = __float_as_uint(BB[nn * PADS + lk8 + tig]);
                bb[nt][1] = __float_as_uint(BB[nn * PADS + lk8 + tig + 4]);
                bs[nt][0] = __float_as_uint(BS[nn * PADS + lk8 + tig]);
                bs[nt][1] = __float_as_uint(BS[nn * PADS + lk8 + tig + 4]);
            }
#pragma unroll
            for (int mt = 0; mt < 2; mt++)
#pragma unroll
                for (int nt = 0; nt < 8; nt++) {
                    mma16n8k8(acc[mt][nt], ab[mt], bb[nt]);
                    mma16n8k8(acc[mt][nt], as_[mt], bb[nt]);
                    mma16n8k8(acc[mt][nt], ab[mt], bs[nt]);
                }
        }
        __syncthreads();
    }

    float bias[8][2];
#pragma unroll
    for (int nt = 0; nt < 8; nt++) {
        const int col = n0 + (wn << 6) + (nt << 3) + (tig << 1);
        float v0 = b1[col], v1 = b1[col + 1];
        if (b2) { v0 += b2[col]; v1 += b2[col + 1]; }
        bias[nt][0] = v0; bias[nt][1] = v1;
    }
#pragma unroll
    for (int mt = 0; mt < 2; mt++)
#pragma unroll
        for (int half = 0; half < 2; half++) {
            const int row = m0 + (wm << 5) + (mt << 4) + gid + (half << 3);
            float* crow = C + (size_t)row * N;
#pragma unroll
            for (int nt = 0; nt < 8; nt++) {
                const int col = n0 + (wn << 6) + (nt << 3) + (tig << 1);
                float2 v;
                v.x = acc[mt][nt][half * 2 + 0] + bias[nt][0];
                v.y = acc[mt][nt][half * 2 + 1] + bias[nt][1];
                *(float2*)(crow + col) = v;
            }
        }
}

// ---------------- init ----------------
__global__ void zero_cnt_kernel() {
    if (threadIdx.x < NG) g_cnt[threadIdx.x] = 0;
}

// ---------------- K2: persistent recurrence, N-split warps ----------------
// 128 CTAs = 16 groups x 8 slices, 1/SM (smem 172KB). Warp w owns output cols
// [w*8, w*8+8) over FULL K=512 -> final accumulators in registers, no reduction.
// hT is b-major: staging is a straight 32KB cp.async memcpy (conflict-free);
// compute reads h as broadcast float4 and W as 2-address broadcast ulonglong2.
__global__ void __launch_bounds__(256) rnn_rec_kernel(const float* __restrict__ w_hh)
{
    extern __shared__ float sm[];
    float* w_t = sm;                 // [512][WPAD] k-major W slice
    float* hT  = sm + H_ * WPAD;     // [BT][HSTR]  b-major h tile

    const int tid = threadIdx.x;
    const int g = blockIdx.x >> 3;
    const int s = blockIdx.x & 7;
    const int n0 = s * NS;
    const int b0 = g * BT;

    // cache W_hh slice: w_t[k][n] = w_hh[n0+n][k]
    for (int i = tid; i < NS * H_; i += 256) {
        int n = i >> 9;
        int k = i & (H_ - 1);
        w_t[k * WPAD + n] = w_hh[(size_t)(n0 + n) * H_ + k];
    }

    const int wid = tid >> 5, lane = tid & 31;
    const int b  = lane >> 1;        // batch row (0..15)
    const int nh = lane & 1;         // col half (0/1)
    const int c0 = wid * 8 + nh * 4; // 4 output cols

    const size_t obase = ((size_t)(b0 + b)) * H_ + n0 + c0;
    const uint32_t hT_u32 = smem_u32(hT);

    __syncthreads();

    for (int t = 0; t < T_; t++) {
        // prefetch xp[t] (independent of the flag)
        const float4 xv = __ldcs((const float4*)&g_xp[(size_t)t * B_ * H_ + obase]);

        // --- acquire h_{t-1} ---
        if (t > 0) {
            if (tid == 0) {
                volatile int* c = g_cnt + g;
                while (*c < NSL * t) __nanosleep(40);
                __threadfence();
            }
            __syncthreads();
            const float* hsrc = g_hs + ((size_t)(t - 1) * B_ + b0) * H_;
#pragma unroll
            for (int j = 0; j < 8; j++) {
                int i4 = tid + (j << 8);          // float4 index 0..2047
                int bb = i4 >> 7;                 // batch row
                int k4 = i4 & 127;                // float4 within row
                cp_async16(hT_u32 + (uint32_t)(bb * HSTR + k4 * 4) * 4,
                           hsrc + (size_t)i4 * 4);
            }
            CP_COMMIT_WAIT();
        } else {
            for (int i = tid; i < BT * HSTR; i += 256) hT[i] = 0.0f;
        }
        __syncthreads();

        // --- compute 4 output cols for batch row b over full K ---
        unsigned long long a0 = 0ull, a1 = 0ull;
        const float* hrow = hT + b * HSTR;
        const float* wcol = w_t + c0;
#pragma unroll 4
        for (int k4 = 0; k4 < 128; k4++) {
            const float4 hv = *(const float4*)(hrow + (k4 << 2));
            const float hh[4] = {hv.x, hv.y, hv.z, hv.w};
#pragma unroll
            for (int c = 0; c < 4; c++) {
                const ulonglong2 wv = *(const ulonglong2*)(wcol + ((k4 << 2) + c) * WPAD);
                const unsigned long long hs2 = f32x2_splat(hh[c]);
                a0 = f32x2_fma(hs2, wv.x, a0);
                a1 = f32x2_fma(hs2, wv.y, a1);
            }
        }

        // --- epilogue: add xp, tanh, store h_t (no cross-warp reduce needed) ---
        {
            const float2 lo = f32x2_unpack(a0);
            const float2 hi = f32x2_unpack(a1);
            float4 r;
            r.x = tanhf(lo.x + xv.x);
            r.y = tanhf(lo.y + xv.y);
            r.z = tanhf(hi.x + xv.z);
            r.w = tanhf(hi.y + xv.w);
            *(float4*)&g_hs[(size_t)t * B_ * H_ + obase] = r;
        }
        __syncthreads();

        // --- release slice s of step t ---
        if (tid == 0) {
            __threadfence();
            atomicAdd(&g_cnt[g], 1);
        }
    }
}

// ---------------- launch ----------------
extern "C" void kernel_launch(void* const* d_in, const int* in_sizes, int n_in,
                              void* d_out, int out_size)
{
    const float* x    = (const float*)d_in[0];
    const float* w_ih = (const float*)d_in[1];
    const float* w_hh = (const float*)d_in[2];
    const float* b_ih = (const float*)d_in[3];
    const float* b_hh = (const float*)d_in[4];
    const float* w_fc = (const float*)d_in[5];
    const float* b_fc = (const float*)d_in[6];
    float* out = (float*)d_out;

    float* xp = nullptr;
    float* hs = nullptr;
    cudaGetSymbolAddress((void**)&xp, g_xp);
    cudaGetSymbolAddress((void**)&hs, g_hs);

    const int rec_smem = (H_ * WPAD + BT * HSTR) * (int)sizeof(float); // 172288
    cudaFuncSetAttribute(rnn_rec_kernel, cudaFuncAttributeMaxDynamicSharedMemorySize, rec_smem);
    cudaFuncSetAttribute(mma_gemm_kernel, cudaFuncAttributeMaxDynamicSharedMemorySize, GEMM_SMEM_BYTES);

    const int M = T_ * B_;

    zero_cnt_kernel<<<1, 32>>>();

    // K1: xp = x @ w_ih^T + (b_ih + b_hh)
    mma_gemm_kernel<<<dim3(H_ / 128, M / 128), 256, GEMM_SMEM_BYTES>>>(x, w_ih, b_ih, b_hh, xp, M, H_, I_);

    // K2: recurrence (persistent, 128 CTAs)
    rnn_rec_kernel<<<NG * NSL, 256, rec_smem>>>(w_hh);

    // K3: out = hs @ w_fc^T + b_fc
    mma_gemm_kernel<<<dim3(I_ / 128, M / 128), 256, GEMM_SMEM_BYTES>>>(hs, w_fc, b_fc, nullptr, out, M, I_, H_);
}

// round 14
// speedup vs baseline: 1.3032x; 1.3032x over previous
#include <cuda_runtime.h>
#include <cuda_bf16.h>
#include <cstdint>

// RNNModel: T=512, B=256, I=256, H=512, fp32.
//   K1: xp = x @ w_ih^T + (b_ih + b_hh)      -> mma.sync 3xTF32 GEMM (proven)
//   K2: h_t = tanh(xp_t + h_{t-1} @ w_hh^T)  -> persistent; bf16x2 mma.sync (W1h1+W1h2+W2h1)
//   K3: out = hs @ w_fc^T + b_fc             -> mma.sync 3xTF32 GEMM (proven)

#define T_ 512
#define B_ 256
#define I_ 256
#define H_ 512

#define NG  16
#define NSL 8
#define BT  16
#define NS  64
#define KS32 260   // u32 (bf16x2) row stride: 260 % 32 == 4 -> frag loads hit 32 distinct banks

__device__ float g_xp[(size_t)T_ * B_ * H_];
__device__ float g_hs[(size_t)T_ * B_ * H_];
__device__ int   g_cnt[NG];

// ---------------- tf32 helpers (GEMM) ----------------
__device__ __forceinline__ uint32_t cvt_tf32(float x) {
    uint32_t r;
    asm("cvt.rna.tf32.f32 %0, %1;" : "=r"(r) : "f"(x));
    return r;
}
__device__ __forceinline__ void split_tf32(float x, float& big, float& small) {
    big = __uint_as_float(cvt_tf32(x));
    small = __uint_as_float(cvt_tf32(x - big));
}
__device__ __forceinline__ void mma16n8k8(float* c, const uint32_t* a, const uint32_t* b) {
    asm volatile("mma.sync.aligned.m16n8k8.row.col.f32.tf32.tf32.f32 "
        "{%0,%1,%2,%3}, {%4,%5,%6,%7}, {%8,%9}, {%0,%1,%2,%3};"
        : "+f"(c[0]), "+f"(c[1]), "+f"(c[2]), "+f"(c[3])
        : "r"(a[0]), "r"(a[1]), "r"(a[2]), "r"(a[3]), "r"(b[0]), "r"(b[1]));
}
__device__ __forceinline__ void mma16n8k16_bf16(float* c, const uint32_t* a, const uint32_t* b) {
    asm volatile("mma.sync.aligned.m16n8k16.row.col.f32.bf16.bf16.f32 "
        "{%0,%1,%2,%3}, {%4,%5,%6,%7}, {%8,%9}, {%0,%1,%2,%3};"
        : "+f"(c[0]), "+f"(c[1]), "+f"(c[2]), "+f"(c[3])
        : "r"(a[0]), "r"(a[1]), "r"(a[2]), "r"(a[3]), "r"(b[0]), "r"(b[1]));
}
__device__ __forceinline__ uint32_t bf2_pack(float f0, float f1) {
    __nv_bfloat162 p = __floats2bfloat162_rn(f0, f1);
    return *reinterpret_cast<uint32_t*>(&p);
}

// ---------------- K1/K3: 3xTF32 mma.sync GEMM (R13 verbatim) ----------------
#define KCHUNK 16
#define PADS 20
#define ARRF (128 * PADS)
#define STGF (4 * ARRF)
#define GEMM_SMEM_BYTES (2 * STGF * 4)   // 81920

__global__ void __launch_bounds__(256, 2) mma_gemm_kernel(
    const float* __restrict__ A, const float* __restrict__ Bm,
    const float* __restrict__ b1, const float* __restrict__ b2,
    float* __restrict__ C, int M, int N, int K)
{
    extern __shared__ float sh[];
    const int tid = threadIdx.x;
    const int m0 = blockIdx.y << 7;
    const int n0 = blockIdx.x << 7;
    const int lane = tid & 31, wid = tid >> 5;
    const int gid = lane >> 2, tig = lane & 3;
    const int wm = wid >> 1, wn = wid & 1;

    const int lrow = tid >> 1;
    const int lko  = (tid & 1) << 3;

    const float* Ap = A + (size_t)(m0 + lrow) * K + lko;
    const float* Bp = Bm + (size_t)(n0 + lrow) * K + lko;

    float acc[2][8][4];
#pragma unroll
    for (int mt = 0; mt < 2; mt++)
#pragma unroll
        for (int nt = 0; nt < 8; nt++)
#pragma unroll
            for (int i = 0; i < 4; i++) acc[mt][nt][i] = 0.0f;

    const int NC = K >> 4;

    float4 ar0 = *(const float4*)(Ap);
    float4 ar1 = *(const float4*)(Ap + 4);
    float4 br0 = *(const float4*)(Bp);
    float4 br1 = *(const float4*)(Bp + 4);

    for (int kc = 0; kc < NC; kc++) {
        const int s = kc & 1;
        float* AB = sh + s * STGF;
        float* AS = AB + ARRF;
        float* BB = AS + ARRF;
        float* BS = BB + ARRF;

        {
            float4 bg, sm;
            const int sa = lrow * PADS + lko;
            split_tf32(ar0.x, bg.x, sm.x); split_tf32(ar0.y, bg.y, sm.y);
            split_tf32(ar0.z, bg.z, sm.z); split_tf32(ar0.w, bg.w, sm.w);
            *(float4*)(AB + sa) = bg; *(float4*)(AS + sa) = sm;
            split_tf32(ar1.x, bg.x, sm.x); split_tf32(ar1.y, bg.y, sm.y);
            split_tf32(ar1.z, bg.z, sm.z); split_tf32(ar1.w, bg.w, sm.w);
            *(float4*)(AB + sa + 4) = bg; *(float4*)(AS + sa + 4) = sm;
            split_tf32(br0.x, bg.x, sm.x); split_tf32(br0.y, bg.y, sm.y);
            split_tf32(br0.z, bg.z, sm.z); split_tf32(br0.w, bg.w, sm.w);
            *(float4*)(BB + sa) = bg; *(float4*)(BS + sa) = sm;
            split_tf32(br1.x, bg.x, sm.x); split_tf32(br1.y, bg.y, sm.y);
            split_tf32(br1.z, bg.z, sm.z); split_tf32(br1.w, bg.w, sm.w);
            *(float4*)(BB + sa + 4) = bg; *(float4*)(BS + sa + 4) = sm;
        }
        __syncthreads();

        if (kc + 1 < NC) {
            const int K0 = (kc + 1) << 4;
            ar0 = *(const float4*)(Ap + K0);
            ar1 = *(const float4*)(Ap + K0 + 4);
            br0 = *(const float4*)(Bp + K0);
            br1 = *(const float4*)(Bp + K0 + 4);
        }

#pragma unroll
        for (int lk8 = 0; lk8 < KCHUNK; lk8 += 8) {
            uint32_t ab[2][4], as_[2][4], bb[8][2], bs[8][2];
#pragma unroll
            for (int mt = 0; mt < 2; mt++) {
                const int r = (wm << 5) + (mt << 4) + gid;
                ab[mt][0]  = __float_as_uint(AB[r * PADS + lk8 + tig]);
                ab[mt][1]  = __float_as_uint(AB[(r + 8) * PADS + lk8 + tig]);
                ab[mt][2]  = __float_as_uint(AB[r * PADS + lk8 + tig + 4]);
                ab[mt][3]  = __float_as_uint(AB[(r + 8) * PADS + lk8 + tig + 4]);
                as_[mt][0] = __float_as_uint(AS[r * PADS + lk8 + tig]);
                as_[mt][1] = __float_as_uint(AS[(r + 8) * PADS + lk8 + tig]);
                as_[mt][2] = __float_as_uint(AS[r * PADS + lk8 + tig + 4]);
                as_[mt][3] = __float_as_uint(AS[(r + 8) * PADS + lk8 + tig + 4]);
            }
#pragma unroll
            for (int nt = 0; nt < 8; nt++) {
                const int nn = (wn << 6) + (nt << 3) + gid;
                bb[nt][0] = __float_as_uint(BB[nn * PADS + lk8 + tig]);
                bb[nt][1] = __float_as_uint(BB[nn * PADS + lk8 + tig + 4]);
                bs[nt][0] = __float_as_uint(BS[nn * PADS + lk8 + tig]);
                bs[nt][1] = __float_as_uint(BS[nn * PADS + lk8 + tig + 4]);
            }
#pragma unroll
            for (int mt = 0; mt < 2; mt++)
#pragma unroll
                for (int nt = 0; nt < 8; nt++) {
                    mma16n8k8(acc[mt][nt], ab[mt], bb[nt]);
                    mma16n8k8(acc[mt][nt], as_[mt], bb[nt]);
                    mma16n8k8(acc[mt][nt], ab[mt], bs[nt]);
                }
        }
        __syncthreads();
    }

    float bias[8][2];
#pragma unroll
    for (int nt = 0; nt < 8; nt++) {
        const int col = n0 + (wn << 6) + (nt << 3) + (tig << 1);
        float v0 = b1[col], v1 = b1[col + 1];
        if (b2) { v0 += b2[col]; v1 += b2[col + 1]; }
        bias[nt][0] = v0; bias[nt][1] = v1;
    }
#pragma unroll
    for (int mt = 0; mt < 2; mt++)
#pragma unroll
        for (int half = 0; half < 2; half++) {
            const int row = m0 + (wm << 5) + (mt << 4) + gid + (half << 3);
            float* crow = C + (size_t)row * N;
#pragma unroll
            for (int nt = 0; nt < 8; nt++) {
                const int col = n0 + (wn << 6) + (nt << 3) + (tig << 1);
                float2 v;
                v.x = acc[mt][nt][half * 2 + 0] + bias[nt][0];
                v.y = acc[mt][nt][half * 2 + 1] + bias[nt][1];
                *(float2*)(crow + col) = v;
            }
        }
}

// ---------------- init ----------------
__global__ void zero_cnt_kernel() {
    if (threadIdx.x < NG) g_cnt[threadIdx.x] = 0;
}

// ---------------- K2: persistent recurrence, bf16x2 mma.sync ----------------
// 128 CTAs = 16 groups x 8 slices, 1/SM. Per step per CTA: D[16b x 64n] over K=512.
// W slice split ONCE into W1,W2 (bf16x2, [n][k] u32-pair layout, stride 260 u32).
// h_{t-1} staged+split each step into H1,H2. Warp w owns n-cols [8w,8w+8):
// 32 k16-blocks x 3 bf16 mma (W1h1 + W1h2 + W2h1), fp32 accum, no reduction.
#define REC_SMEM_BYTES ((2 * 64 * KS32 + 2 * 16 * KS32) * 4)   // 166400

__global__ void __launch_bounds__(256) rnn_rec_kernel(const float* __restrict__ w_hh)
{
    extern __shared__ uint32_t su[];
    uint32_t* W1 = su;                    // [64][260] bf16x2 pairs (k = 2*idx, 2*idx+1)
    uint32_t* W2 = W1 + 64 * KS32;
    uint32_t* H1 = W2 + 64 * KS32;        // [16][260]
    uint32_t* H2 = H1 + 16 * KS32;

    const int tid = threadIdx.x;
    const int g = blockIdx.x >> 3;
    const int s = blockIdx.x & 7;
    const int n0 = s * NS;
    const int b0 = g * BT;

    // split W slice once: W[n][k] -> bf16 big + bf16 residual (packed pairs)
    for (int idx = tid; idx < 64 * 256; idx += 256) {
        const int n = idx >> 8, kp = idx & 255;
        const float f0 = w_hh[(size_t)(n0 + n) * H_ + 2 * kp];
        const float f1 = w_hh[(size_t)(n0 + n) * H_ + 2 * kp + 1];
        const __nv_bfloat162 big = __floats2bfloat162_rn(f0, f1);
        const float r0 = f0 - __low2float(big);
        const float r1 = f1 - __high2float(big);
        W1[n * KS32 + kp] = *reinterpret_cast<const uint32_t*>(&big);
        W2[n * KS32 + kp] = bf2_pack(r0, r1);
    }
    // zero h arrays (h_{-1} = 0); H1,H2 contiguous
    for (int i = tid; i < 2 * 16 * KS32; i += 256) H1[i] = 0u;

    const int wid = tid >> 5, lane = tid & 31;
    const int gid = lane >> 2, tig = lane & 3;

    const uint32_t* h1a = H1 + gid * KS32;
    const uint32_t* h1b = H1 + (gid + 8) * KS32;
    const uint32_t* h2a = H2 + gid * KS32;
    const uint32_t* h2b = H2 + (gid + 8) * KS32;
    const uint32_t* w1p = W1 + (wid * 8 + gid) * KS32;
    const uint32_t* w2p = W2 + (wid * 8 + gid) * KS32;

    // staging mapping: thread -> (batch row r, 32-float segment seg)
    const int r_st = tid & 15, seg = tid >> 4;
    uint32_t* d1 = H1 + r_st * KS32 + seg * 16;
    uint32_t* d2 = H2 + r_st * KS32 + seg * 16;

    // epilogue mapping: lane (gid,tig) of warp wid -> rows gid/gid+8, cols 2tig..+1
    const size_t ob1 = ((size_t)(b0 + gid)) * H_ + n0 + wid * 8 + 2 * tig;
    const size_t ob2 = ob1 + (size_t)8 * H_;

    __syncthreads();

    for (int t = 0; t < T_; t++) {
        const size_t tb = (size_t)t * B_ * H_;
        // prefetch xp[t] (independent of flag)
        const float2 xv1 = __ldcs((const float2*)(g_xp + tb + ob1));
        const float2 xv2 = __ldcs((const float2*)(g_xp + tb + ob2));

        // --- acquire h_{t-1}, stage + bf16x2 split ---
        if (t > 0) {
            if (tid == 0) {
                volatile int* c = g_cnt + g;
                while (*c < NSL * t) __nanosleep(40);
                __threadfence();
            }
            __syncthreads();
            const float* src = g_hs + (size_t)(t - 1) * B_ * H_
                             + (size_t)(b0 + r_st) * H_ + seg * 32;
#pragma unroll
            for (int q = 0; q < 4; q++) {
                const float4 v0 = __ldcg((const float4*)(src + 8 * q));
                const float4 v1 = __ldcg((const float4*)(src + 8 * q + 4));
                uint4 p1, p2;
                {
                    __nv_bfloat162 b = __floats2bfloat162_rn(v0.x, v0.y);
                    p1.x = *reinterpret_cast<uint32_t*>(&b);
                    p2.x = bf2_pack(v0.x - __low2float(b), v0.y - __high2float(b));
                }
                {
                    __nv_bfloat162 b = __floats2bfloat162_rn(v0.z, v0.w);
                    p1.y = *reinterpret_cast<uint32_t*>(&b);
                    p2.y = bf2_pack(v0.z - __low2float(b), v0.w - __high2float(b));
                }
                {
                    __nv_bfloat162 b = __floats2bfloat162_rn(v1.x, v1.y);
                    p1.z = *reinterpret_cast<uint32_t*>(&b);
                    p2.z = bf2_pack(v1.x - __low2float(b), v1.y - __high2float(b));
                }
                {
                    __nv_bfloat162 b = __floats2bfloat162_rn(v1.z, v1.w);
                    p1.w = *reinterpret_cast<uint32_t*>(&b);
                    p2.w = bf2_pack(v1.z - __low2float(b), v1.w - __high2float(b));
                }
                *(uint4*)(d1 + 4 * q) = p1;
                *(uint4*)(d2 + 4 * q) = p2;
            }
            __syncthreads();
        }

        // --- compute: 32 k16-blocks x 3 bf16 mma ---
        float c[4] = {0.0f, 0.0f, 0.0f, 0.0f};
#pragma unroll 8
        for (int kb = 0; kb < 32; kb++) {
            const int off = kb * 8 + tig;
            uint32_t A1[4], A2[4], B1[2], B2[2];
            A1[0] = h1a[off];     A1[1] = h1b[off];
            A1[2] = h1a[off + 4]; A1[3] = h1b[off + 4];
            A2[0] = h2a[off];     A2[1] = h2b[off];
            A2[2] = h2a[off + 4]; A2[3] = h2b[off + 4];
            B1[0] = w1p[off];     B1[1] = w1p[off + 4];
            B2[0] = w2p[off];     B2[1] = w2p[off + 4];
            mma16n8k16_bf16(c, A1, B1);
            mma16n8k16_bf16(c, A2, B1);
            mma16n8k16_bf16(c, A1, B2);
        }

        // --- epilogue: add xp, tanh, store h_t slice ---
        {
            float2 o1, o2;
            o1.x = tanhf(c[0] + xv1.x);
            o1.y = tanhf(c[1] + xv1.y);
            o2.x = tanhf(c[2] + xv2.x);
            o2.y = tanhf(c[3] + xv2.y);
            *(float2*)(g_hs + tb + ob1) = o1;
            *(float2*)(g_hs + tb + ob2) = o2;
        }
        __syncthreads();

        // --- release slice s of step t ---
        if (tid == 0) {
            __threadfence();
            atomicAdd(&g_cnt[g], 1);
        }
    }
}

// ---------------- launch ----------------
extern "C" void kernel_launch(void* const* d_in, const int* in_sizes, int n_in,
                              void* d_out, int out_size)
{
    const float* x    = (const float*)d_in[0];
    const float* w_ih = (const float*)d_in[1];
    const float* w_hh = (const float*)d_in[2];
    const float* b_ih = (const float*)d_in[3];
    const float* b_hh = (const float*)d_in[4];
    const float* w_fc = (const float*)d_in[5];
    const float* b_fc = (const float*)d_in[6];
    float* out = (float*)d_out;

    float* xp = nullptr;
    float* hs = nullptr;
    cudaGetSymbolAddress((void**)&xp, g_xp);
    cudaGetSymbolAddress((void**)&hs, g_hs);

    cudaFuncSetAttribute(rnn_rec_kernel, cudaFuncAttributeMaxDynamicSharedMemorySize, REC_SMEM_BYTES);
    cudaFuncSetAttribute(mma_gemm_kernel, cudaFuncAttributeMaxDynamicSharedMemorySize, GEMM_SMEM_BYTES);

    const int M = T_ * B_;

    zero_cnt_kernel<<<1, 32>>>();

    // K1: xp = x @ w_ih^T + (b_ih + b_hh)
    mma_gemm_kernel<<<dim3(H_ / 128, M / 128), 256, GEMM_SMEM_BYTES>>>(x, w_ih, b_ih, b_hh, xp, M, H_, I_);

    // K2: recurrence (persistent, 128 CTAs, bf16x2 tensor-core steps)
    rnn_rec_kernel<<<NG * NSL, 256, REC_SMEM_BYTES>>>(w_hh);

    // K3: out = hs @ w_fc^T + b_fc
    mma_gemm_kernel<<<dim3(I_ / 128, M / 128), 256, GEMM_SMEM_BYTES>>>(hs, w_fc, b_fc, nullptr, out, M, I_, H_);
}

// round 15
// speedup vs baseline: 1.6765x; 1.2865x over previous
#include <cuda_runtime.h>
#include <cuda_bf16.h>
#include <cstdint>

// RNNModel: T=512, B=256, I=256, H=512, fp32.
//   K1: xp = x @ w_ih^T + (b_ih + b_hh)      -> mma.sync 3xTF32 GEMM (proven, unchanged)
//   K2: h_t = tanh(xp_t + h_{t-1} @ w_hh^T)  -> bf16x2 mma.sync; producers publish pre-split h;
//                                               consumers cp.async direct; acq/rel scoped atomics
//   K3: out = hs @ w_fc^T + b_fc             -> mma.sync 3xTF32 GEMM (proven, unchanged)

#define T_ 512
#define B_ 256
#define I_ 256
#define H_ 512

#define NG  16
#define NSL 8
#define BT  16
#define NS  64
#define KS32 260   // u32 row stride: 260 % 32 == 4 -> mma frag loads hit 32 distinct banks

__device__ float    g_xp[(size_t)T_ * B_ * H_];
__device__ float    g_hs[(size_t)T_ * B_ * H_];
__device__ uint32_t g_h1[2 * B_ * (H_ / 2)];   // double-buffered bf16x2 big
__device__ uint32_t g_h2[2 * B_ * (H_ / 2)];   // double-buffered bf16x2 residual
__device__ int      g_cnt[NG];

// ---------------- helpers ----------------
__device__ __forceinline__ uint32_t smem_u32(const void* p) {
    uint32_t a;
    asm("{ .reg .u64 t; cvta.to.shared.u64 t, %1; cvt.u32.u64 %0, t; }" : "=r"(a) : "l"(p));
    return a;
}
__device__ __forceinline__ void cp_async16(uint32_t saddr, const void* gptr) {
    asm volatile("cp.async.ca.shared.global [%0], [%1], 16;" :: "r"(saddr), "l"(gptr));
}
#define CP_COMMIT_WAIT() \
    asm volatile("cp.async.commit_group;\n\tcp.async.wait_group 0;" ::: "memory")

__device__ __forceinline__ uint32_t cvt_tf32(float x) {
    uint32_t r;
    asm("cvt.rna.tf32.f32 %0, %1;" : "=r"(r) : "f"(x));
    return r;
}
__device__ __forceinline__ void split_tf32(float x, float& big, float& small) {
    big = __uint_as_float(cvt_tf32(x));
    small = __uint_as_float(cvt_tf32(x - big));
}
__device__ __forceinline__ void mma16n8k8(float* c, const uint32_t* a, const uint32_t* b) {
    asm volatile("mma.sync.aligned.m16n8k8.row.col.f32.tf32.tf32.f32 "
        "{%0,%1,%2,%3}, {%4,%5,%6,%7}, {%8,%9}, {%0,%1,%2,%3};"
        : "+f"(c[0]), "+f"(c[1]), "+f"(c[2]), "+f"(c[3])
        : "r"(a[0]), "r"(a[1]), "r"(a[2]), "r"(a[3]), "r"(b[0]), "r"(b[1]));
}
__device__ __forceinline__ void mma16n8k16_bf16(float* c, const uint32_t* a, const uint32_t* b) {
    asm volatile("mma.sync.aligned.m16n8k16.row.col.f32.bf16.bf16.f32 "
        "{%0,%1,%2,%3}, {%4,%5,%6,%7}, {%8,%9}, {%0,%1,%2,%3};"
        : "+f"(c[0]), "+f"(c[1]), "+f"(c[2]), "+f"(c[3])
        : "r"(a[0]), "r"(a[1]), "r"(a[2]), "r"(a[3]), "r"(b[0]), "r"(b[1]));
}
__device__ __forceinline__ uint32_t bf2_pack(float f0, float f1) {
    __nv_bfloat162 p = __floats2bfloat162_rn(f0, f1);
    return *reinterpret_cast<uint32_t*>(&p);
}

// ---------------- K1/K3: 3xTF32 mma.sync GEMM (R13 verbatim) ----------------
#define KCHUNK 16
#define PADS 20
#define ARRF (128 * PADS)
#define STGF (4 * ARRF)
#define GEMM_SMEM_BYTES (2 * STGF * 4)   // 81920

__global__ void __launch_bounds__(256, 2) mma_gemm_kernel(
    const float* __restrict__ A, const float* __restrict__ Bm,
    const float* __restrict__ b1, const float* __restrict__ b2,
    float* __restrict__ C, int M, int N, int K)
{
    extern __shared__ float sh[];
    const int tid = threadIdx.x;
    const int m0 = blockIdx.y << 7;
    const int n0 = blockIdx.x << 7;
    const int lane = tid & 31, wid = tid >> 5;
    const int gid = lane >> 2, tig = lane & 3;
    const int wm = wid >> 1, wn = wid & 1;

    const int lrow = tid >> 1;
    const int lko  = (tid & 1) << 3;

    const float* Ap = A + (size_t)(m0 + lrow) * K + lko;
    const float* Bp = Bm + (size_t)(n0 + lrow) * K + lko;

    float acc[2][8][4];
#pragma unroll
    for (int mt = 0; mt < 2; mt++)
#pragma unroll
        for (int nt = 0; nt < 8; nt++)
#pragma unroll
            for (int i = 0; i < 4; i++) acc[mt][nt][i] = 0.0f;

    const int NC = K >> 4;

    float4 ar0 = *(const float4*)(Ap);
    float4 ar1 = *(const float4*)(Ap + 4);
    float4 br0 = *(const float4*)(Bp);
    float4 br1 = *(const float4*)(Bp + 4);

    for (int kc = 0; kc < NC; kc++) {
        const int s = kc & 1;
        float* AB = sh + s * STGF;
        float* AS = AB + ARRF;
        float* BB = AS + ARRF;
        float* BS = BB + ARRF;

        {
            float4 bg, sm;
            const int sa = lrow * PADS + lko;
            split_tf32(ar0.x, bg.x, sm.x); split_tf32(ar0.y, bg.y, sm.y);
            split_tf32(ar0.z, bg.z, sm.z); split_tf32(ar0.w, bg.w, sm.w);
            *(float4*)(AB + sa) = bg; *(float4*)(AS + sa) = sm;
            split_tf32(ar1.x, bg.x, sm.x); split_tf32(ar1.y, bg.y, sm.y);
            split_tf32(ar1.z, bg.z, sm.z); split_tf32(ar1.w, bg.w, sm.w);
            *(float4*)(AB + sa + 4) = bg; *(float4*)(AS + sa + 4) = sm;
            split_tf32(br0.x, bg.x, sm.x); split_tf32(br0.y, bg.y, sm.y);
            split_tf32(br0.z, bg.z, sm.z); split_tf32(br0.w, bg.w, sm.w);
            *(float4*)(BB + sa) = bg; *(float4*)(BS + sa) = sm;
            split_tf32(br1.x, bg.x, sm.x); split_tf32(br1.y, bg.y, sm.y);
            split_tf32(br1.z, bg.z, sm.z); split_tf32(br1.w, bg.w, sm.w);
            *(float4*)(BB + sa + 4) = bg; *(float4*)(BS + sa + 4) = sm;
        }
        __syncthreads();

        if (kc + 1 < NC) {
            const int K0 = (kc + 1) << 4;
            ar0 = *(const float4*)(Ap + K0);
            ar1 = *(const float4*)(Ap + K0 + 4);
            br0 = *(const float4*)(Bp + K0);
            br1 = *(const float4*)(Bp + K0 + 4);
        }

#pragma unroll
        for (int lk8 = 0; lk8 < KCHUNK; lk8 += 8) {
            uint32_t ab[2][4], as_[2][4], bb[8][2], bs[8][2];
#pragma unroll
            for (int mt = 0; mt < 2; mt++) {
                const int r = (wm << 5) + (mt << 4) + gid;
                ab[mt][0]  = __float_as_uint(AB[r * PADS + lk8 + tig]);
                ab[mt][1]  = __float_as_uint(AB[(r + 8) * PADS + lk8 + tig]);
                ab[mt][2]  = __float_as_uint(AB[r * PADS + lk8 + tig + 4]);
                ab[mt][3]  = __float_as_uint(AB[(r + 8) * PADS + lk8 + tig + 4]);
                as_[mt][0] = __float_as_uint(AS[r * PADS + lk8 + tig]);
                as_[mt][1] = __float_as_uint(AS[(r + 8) * PADS + lk8 + tig]);
                as_[mt][2] = __float_as_uint(AS[r * PADS + lk8 + tig + 4]);
                as_[mt][3] = __float_as_uint(AS[(r + 8) * PADS + lk8 + tig + 4]);
            }
#pragma unroll
            for (int nt = 0; nt < 8; nt++) {
                const int nn = (wn << 6) + (nt << 3) + gid;
                bb[nt][0] = __float_as_uint(BB[nn * PADS + lk8 + tig]);
                bb[nt][1] = __float_as_uint(BB[nn * PADS + lk8 + tig + 4]);
                bs[nt][0] = __float_as_uint(BS[nn * PADS + lk8 + tig]);
                bs[nt][1] = __float_as_uint(BS[nn * PADS + lk8 + tig + 4]);
            }
#pragma unroll
            for (int mt = 0; mt < 2; mt++)
#pragma unroll
                for (int nt = 0; nt < 8; nt++) {
                    mma16n8k8(acc[mt][nt], ab[mt], bb[nt]);
                    mma16n8k8(acc[mt][nt], as_[mt], bb[nt]);
                    mma16n8k8(acc[mt][nt], ab[mt], bs[nt]);
                }
        }
        __syncthreads();
    }

    float bias[8][2];
#pragma unroll
    for (int nt = 0; nt < 8; nt++) {
        const int col = n0 + (wn << 6) + (nt << 3) + (tig << 1);
        float v0 = b1[col], v1 = b1[col + 1];
        if (b2) { v0 += b2[col]; v1 += b2[col + 1]; }
        bias[nt][0] = v0; bias[nt][1] = v1;
    }
#pragma unroll
    for (int mt = 0; mt < 2; mt++)
#pragma unroll
        for (int half = 0; half < 2; half++) {
            const int row = m0 + (wm << 5) + (mt << 4) + gid + (half << 3);
            float* crow = C + (size_t)row * N;
#pragma unroll
            for (int nt = 0; nt < 8; nt++) {
                const int col = n0 + (wn << 6) + (nt << 3) + (tig << 1);
                float2 v;
                v.x = acc[mt][nt][half * 2 + 0] + bias[nt][0];
                v.y = acc[mt][nt][half * 2 + 1] + bias[nt][1];
                *(float2*)(crow + col) = v;
            }
        }
}

// ---------------- init ----------------
__global__ void zero_cnt_kernel() {
    if (threadIdx.x < NG) g_cnt[threadIdx.x] = 0;
}

// ---------------- K2: persistent recurrence, bf16x2 mma.sync, pre-split h ----------------
// 128 CTAs = 16 groups x 8 slices, 1/SM. Producers publish h already split (g_h1/g_h2,
// double-buffered by t&1); consumers cp.async both arrays straight into stride-260 smem.
// Acquire: ALL threads spin on ld.acquire of the group counter (no tid0 relay).
// Release: red.release.gpu.add after one syncthreads.
// Double-buffer safety: flag >= 8t means every CTA finished step t-1, i.e. staged h_{t-2};
// producer at step t overwrites exactly the h_{t-2} slot -> no reader remains.
#define REC_SMEM_BYTES ((2 * 64 * KS32 + 2 * 16 * KS32) * 4)   // 166400

__global__ void __launch_bounds__(256) rnn_rec_kernel(const float* __restrict__ w_hh)
{
    extern __shared__ uint32_t su[];
    uint32_t* W1 = su;                    // [64][260] bf16x2 pairs
    uint32_t* W2 = W1 + 64 * KS32;
    uint32_t* H1 = W2 + 64 * KS32;        // [16][260]
    uint32_t* H2 = H1 + 16 * KS32;

    const int tid = threadIdx.x;
    const int g = blockIdx.x >> 3;
    const int s = blockIdx.x & 7;
    const int n0 = s * NS;
    const int b0 = g * BT;

    // split W slice once
    for (int idx = tid; idx < 64 * 256; idx += 256) {
        const int n = idx >> 8, kp = idx & 255;
        const float f0 = w_hh[(size_t)(n0 + n) * H_ + 2 * kp];
        const float f1 = w_hh[(size_t)(n0 + n) * H_ + 2 * kp + 1];
        const __nv_bfloat162 big = __floats2bfloat162_rn(f0, f1);
        const float r0 = f0 - __low2float(big);
        const float r1 = f1 - __high2float(big);
        W1[n * KS32 + kp] = *reinterpret_cast<const uint32_t*>(&big);
        W2[n * KS32 + kp] = bf2_pack(r0, r1);
    }
    for (int i = tid; i < 2 * 16 * KS32; i += 256) H1[i] = 0u;

    const int wid = tid >> 5, lane = tid & 31;
    const int gid = lane >> 2, tig = lane & 3;

    const uint32_t* h1a = H1 + gid * KS32;
    const uint32_t* h1b = H1 + (gid + 8) * KS32;
    const uint32_t* h2a = H2 + gid * KS32;
    const uint32_t* h2b = H2 + (gid + 8) * KS32;
    const uint32_t* w1p = W1 + (wid * 8 + gid) * KS32;
    const uint32_t* w2p = W2 + (wid * 8 + gid) * KS32;

    // staging mapping: 1024 16B-chunks per array; thread does 4 per array
    const uint32_t H1u = smem_u32(H1);
    const uint32_t H2u = smem_u32(H2);

    // epilogue mapping
    const size_t ob1 = ((size_t)(b0 + gid)) * H_ + n0 + wid * 8 + 2 * tig;
    const size_t ob2 = ob1 + (size_t)8 * H_;
    const int    kp1 = (b0 + gid) * 256 + (n0 >> 1) + wid * 4 + tig;   // u32 index in [B][256]
    const int    kp2 = kp1 + 8 * 256;

    const int* cntp = &g_cnt[g];

    __syncthreads();

    for (int t = 0; t < T_; t++) {
        const size_t tb = (size_t)t * B_ * H_;
        const float2 xv1 = __ldcs((const float2*)(g_xp + tb + ob1));
        const float2 xv2 = __ldcs((const float2*)(g_xp + tb + ob2));

        // --- acquire h_{t-1} (all threads) + direct cp.async of pre-split h ---
        if (t > 0) {
            unsigned int v;
            do {
                asm volatile("ld.acquire.gpu.global.b32 %0, [%1];" : "=r"(v) : "l"(cntp));
            } while (v < (unsigned int)(NSL * t));
            const int buf = (t - 1) & 1;
            const uint32_t* s1 = g_h1 + (size_t)buf * B_ * 256;
            const uint32_t* s2 = g_h2 + (size_t)buf * B_ * 256;
#pragma unroll
            for (int j = 0; j < 4; j++) {
                const int c = tid + (j << 8);         // 0..1023
                const int row = c >> 6, q = c & 63;   // row 0..15, 16B-chunk 0..63
                const uint32_t dof = (uint32_t)(row * KS32 + q * 4) * 4;
                const size_t   sof = (size_t)(b0 + row) * 256 + q * 4;
                cp_async16(H1u + dof, s1 + sof);
                cp_async16(H2u + dof, s2 + sof);
            }
            CP_COMMIT_WAIT();
        }
        __syncthreads();

        // --- compute: 32 k16-blocks x 3 bf16 mma ---
        float c[4] = {0.0f, 0.0f, 0.0f, 0.0f};
#pragma unroll 8
        for (int kb = 0; kb < 32; kb++) {
            const int off = kb * 8 + tig;
            uint32_t A1[4], A2[4], B1[2], B2[2];
            A1[0] = h1a[off];     A1[1] = h1b[off];
            A1[2] = h1a[off + 4]; A1[3] = h1b[off + 4];
            A2[0] = h2a[off];     A2[1] = h2b[off];
            A2[2] = h2a[off + 4]; A2[3] = h2b[off + 4];
            B1[0] = w1p[off];     B1[1] = w1p[off + 4];
            B2[0] = w2p[off];     B2[1] = w2p[off + 4];
            mma16n8k16_bf16(c, A1, B1);
            mma16n8k16_bf16(c, A2, B1);
            mma16n8k16_bf16(c, A1, B2);
        }

        // --- epilogue: tanh, store fp32 (K3) + pre-split bf16x2 (next step) ---
        {
            const int buf = t & 1;
            uint32_t* d1 = g_h1 + (size_t)buf * B_ * 256;
            uint32_t* d2 = g_h2 + (size_t)buf * B_ * 256;
            float2 o1, o2;
            o1.x = tanhf(c[0] + xv1.x);
            o1.y = tanhf(c[1] + xv1.y);
            o2.x = tanhf(c[2] + xv2.x);
            o2.y = tanhf(c[3] + xv2.y);
            *(float2*)(g_hs + tb + ob1) = o1;
            *(float2*)(g_hs + tb + ob2) = o2;
            {
                const __nv_bfloat162 b = __floats2bfloat162_rn(o1.x, o1.y);
                d1[kp1] = *reinterpret_cast<const uint32_t*>(&b);
                d2[kp1] = bf2_pack(o1.x - __low2float(b), o1.y - __high2float(b));
            }
            {
                const __nv_bfloat162 b = __floats2bfloat162_rn(o2.x, o2.y);
                d1[kp2] = *reinterpret_cast<const uint32_t*>(&b);
                d2[kp2] = bf2_pack(o2.x - __low2float(b), o2.y - __high2float(b));
            }
        }
        __syncthreads();

        // --- release slice s of step t ---
        if (tid == 0) {
            asm volatile("red.release.gpu.global.add.u32 [%0], %1;"
                         :: "l"(cntp), "r"(1u) : "memory");
        }
    }
}

// ---------------- launch ----------------
extern "C" void kernel_launch(void* const* d_in, const int* in_sizes, int n_in,
                              void* d_out, int out_size)
{
    const float* x    = (const float*)d_in[0];
    const float* w_ih = (const float*)d_in[1];
    const float* w_hh = (const float*)d_in[2];
    const float* b_ih = (const float*)d_in[3];
    const float* b_hh = (const float*)d_in[4];
    const float* w_fc = (const float*)d_in[5];
    const float* b_fc = (const float*)d_in[6];
    float* out = (float*)d_out;

    float* xp = nullptr;
    float* hs = nullptr;
    cudaGetSymbolAddress((void**)&xp, g_xp);
    cudaGetSymbolAddress((void**)&hs, g_hs);

    cudaFuncSetAttribute(rnn_rec_kernel, cudaFuncAttributeMaxDynamicSharedMemorySize, REC_SMEM_BYTES);
    cudaFuncSetAttribute(mma_gemm_kernel, cudaFuncAttributeMaxDynamicSharedMemorySize, GEMM_SMEM_BYTES);

    const int M = T_ * B_;

    zero_cnt_kernel<<<1, 32>>>();

    // K1: xp = x @ w_ih^T + (b_ih + b_hh)
    mma_gemm_kernel<<<dim3(H_ / 128, M / 128), 256, GEMM_SMEM_BYTES>>>(x, w_ih, b_ih, b_hh, xp, M, H_, I_);

    // K2: recurrence (persistent, 128 CTAs, bf16x2 tensor-core steps)
    rnn_rec_kernel<<<NG * NSL, 256, REC_SMEM_BYTES>>>(w_hh);

    // K3: out = hs @ w_fc^T + b_fc
    mma_gemm_kernel<<<dim3(I_ / 128, M / 128), 256, GEMM_SMEM_BYTES>>>(hs, w_fc, b_fc, nullptr, out, M, I_, H_);
}

// round 16
// speedup vs baseline: 1.9690x; 1.1745x over previous
#include <cuda_runtime.h>
#include <cuda_bf16.h>
#include <cstdint>

// RNNModel: T=512, B=256, I=256, H=512, fp32.
//   K1: xp = x @ w_ih^T + (b_ih+b_hh)   -> 3xbf16 mma.sync k16 GEMM (fp32 operands, split in loader)
//   K2: h_t = tanh(xp_t + h @ w_hh^T)   -> bf16x2 mma.sync persistent (R15 core); h published
//                                          pre-split to FULL-T g_h1f/g_h2f (g_hs eliminated)
//   K3: out = hs @ w_fc^T + b_fc        -> 3xbf16 GEMM, A read pre-split (no conversion, half bytes)

#define T_ 512
#define B_ 256
#define I_ 256
#define H_ 512

#define NG  16
#define NSL 8
#define BT  16
#define NS  64
#define KS32 260   // K2 smem u32 row stride (frag loads hit 32 banks)

__device__ float    g_xp[(size_t)T_ * B_ * H_];
__device__ uint32_t g_h1f[(size_t)T_ * B_ * (H_ / 2)];   // bf16x2 big,  full history
__device__ uint32_t g_h2f[(size_t)T_ * B_ * (H_ / 2)];   // bf16x2 resid, full history
__device__ int      g_cnt[NG];

// ---------------- helpers ----------------
__device__ __forceinline__ uint32_t smem_u32(const void* p) {
    uint32_t a;
    asm("{ .reg .u64 t; cvta.to.shared.u64 t, %1; cvt.u32.u64 %0, t; }" : "=r"(a) : "l"(p));
    return a;
}
__device__ __forceinline__ void cp_async16(uint32_t saddr, const void* gptr) {
    asm volatile("cp.async.ca.shared.global [%0], [%1], 16;" :: "r"(saddr), "l"(gptr));
}
#define CP_COMMIT_WAIT() \
    asm volatile("cp.async.commit_group;\n\tcp.async.wait_group 0;" ::: "memory")

__device__ __forceinline__ void mma16n8k16_bf16(float* c, const uint32_t* a, const uint32_t* b) {
    asm volatile("mma.sync.aligned.m16n8k16.row.col.f32.bf16.bf16.f32 "
        "{%0,%1,%2,%3}, {%4,%5,%6,%7}, {%8,%9}, {%0,%1,%2,%3};"
        : "+f"(c[0]), "+f"(c[1]), "+f"(c[2]), "+f"(c[3])
        : "r"(a[0]), "r"(a[1]), "r"(a[2]), "r"(a[3]), "r"(b[0]), "r"(b[1]));
}
__device__ __forceinline__ uint32_t bf2_pack(float f0, float f1) {
    __nv_bfloat162 p = __floats2bfloat162_rn(f0, f1);
    return *reinterpret_cast<uint32_t*>(&p);
}
// split two floats into (big pair, residual pair)
__device__ __forceinline__ void split_pair(float f0, float f1, uint32_t& big, uint32_t& res) {
    const __nv_bfloat162 b = __floats2bfloat162_rn(f0, f1);
    big = *reinterpret_cast<const uint32_t*>(&b);
    res = bf2_pack(f0 - __low2float(b), f1 - __high2float(b));
}

// ================= 3xbf16 GEMM common geometry =================
// CTA 128x128, 8 warps (4m x 2n), warp tile 32x64. K-chunk = 32 floats = 16 u32 pairs.
// Smem per stage: A1,A2,B1,B2 each [128][PADB] u32. Double buffered.
#define PADB 20
#define ARRU (128 * PADB)
#define STGU (4 * ARRU)
#define GEMM_SMEM_BYTES (2 * STGU * 4)   // 81920

// compute one K-chunk (16 pairs = 2 x k16 blocks), 3-pass bf16
#define BF16_CHUNK_COMPUTE(A1p_, A2p_, B1p_, B2p_)                                   \
    do {                                                                             \
        _Pragma("unroll")                                                            \
        for (int kb = 0; kb < 2; kb++) {                                             \
            const int off = kb * 8 + tig;                                            \
            uint32_t a1[2][4], a2[2][4], b1f[8][2], b2f[8][2];                       \
            _Pragma("unroll")                                                        \
            for (int mt = 0; mt < 2; mt++) {                                         \
                const int r = (wm << 5) + (mt << 4) + gid;                           \
                a1[mt][0] = (A1p_)[r * PADB + off];                                  \
                a1[mt][1] = (A1p_)[(r + 8) * PADB + off];                            \
                a1[mt][2] = (A1p_)[r * PADB + off + 4];                              \
                a1[mt][3] = (A1p_)[(r + 8) * PADB + off + 4];                        \
                a2[mt][0] = (A2p_)[r * PADB + off];                                  \
                a2[mt][1] = (A2p_)[(r + 8) * PADB + off];                            \
                a2[mt][2] = (A2p_)[r * PADB + off + 4];                              \
                a2[mt][3] = (A2p_)[(r + 8) * PADB + off + 4];                        \
            }                                                                        \
            _Pragma("unroll")                                                        \
            for (int nt = 0; nt < 8; nt++) {                                         \
                const int nn = (wn << 6) + (nt << 3) + gid;                          \
                b1f[nt][0] = (B1p_)[nn * PADB + off];                                \
                b1f[nt][1] = (B1p_)[nn * PADB + off + 4];                            \
                b2f[nt][0] = (B2p_)[nn * PADB + off];                                \
                b2f[nt][1] = (B2p_)[nn * PADB + off + 4];                            \
            }                                                                        \
            _Pragma("unroll")                                                        \
            for (int mt = 0; mt < 2; mt++)                                           \
                _Pragma("unroll")                                                    \
                for (int nt = 0; nt < 8; nt++) {                                     \
                    mma16n8k16_bf16(acc[mt][nt], a1[mt], b1f[nt]);                   \
                    mma16n8k16_bf16(acc[mt][nt], a2[mt], b1f[nt]);                   \
                    mma16n8k16_bf16(acc[mt][nt], a1[mt], b2f[nt]);                   \
                }                                                                    \
        }                                                                            \
    } while (0)

#define BF16_EPILOGUE()                                                              \
    do {                                                                             \
        float bias[8][2];                                                            \
        _Pragma("unroll")                                                            \
        for (int nt = 0; nt < 8; nt++) {                                             \
            const int col = n0 + (wn << 6) + (nt << 3) + (tig << 1);                 \
            float v0 = b1[col], v1 = b1[col + 1];                                    \
            if (b2) { v0 += b2[col]; v1 += b2[col + 1]; }                            \
            bias[nt][0] = v0; bias[nt][1] = v1;                                      \
        }                                                                            \
        _Pragma("unroll")                                                            \
        for (int mt = 0; mt < 2; mt++)                                               \
            _Pragma("unroll")                                                        \
            for (int half = 0; half < 2; half++) {                                   \
                const int row = m0 + (wm << 5) + (mt << 4) + gid + (half << 3);      \
                float* crow = C + (size_t)row * N;                                   \
                _Pragma("unroll")                                                    \
                for (int nt = 0; nt < 8; nt++) {                                     \
                    const int col = n0 + (wn << 6) + (nt << 3) + (tig << 1);         \
                    float2 v;                                                        \
                    v.x = acc[mt][nt][half * 2 + 0] + bias[nt][0];                   \
                    v.y = acc[mt][nt][half * 2 + 1] + bias[nt][1];                   \
                    *(float2*)(crow + col) = v;                                      \
                }                                                                    \
            }                                                                        \
    } while (0)

// ---------------- K1: fp32 A,B -> split in loader ----------------
__global__ void __launch_bounds__(256, 2) bf16_gemm_f32_kernel(
    const float* __restrict__ A, const float* __restrict__ Bm,
    const float* __restrict__ b1, const float* __restrict__ b2,
    float* __restrict__ C, int M, int N, int K)
{
    extern __shared__ uint32_t su[];
    const int tid = threadIdx.x;
    const int m0 = blockIdx.y << 7;
    const int n0 = blockIdx.x << 7;
    const int lane = tid & 31, wid = tid >> 5;
    const int gid = lane >> 2, tig = lane & 3;
    const int wm = wid >> 1, wn = wid & 1;

    const int lrow = tid >> 1;
    const int lko  = (tid & 1) << 4;       // float offset (0 or 16)
    const int sa   = lrow * PADB + (lko >> 1);

    const float* Ap = A + (size_t)(m0 + lrow) * K + lko;
    const float* Bp = Bm + (size_t)(n0 + lrow) * K + lko;

    float acc[2][8][4];
#pragma unroll
    for (int mt = 0; mt < 2; mt++)
#pragma unroll
        for (int nt = 0; nt < 8; nt++)
#pragma unroll
            for (int i = 0; i < 4; i++) acc[mt][nt][i] = 0.0f;

    const int NC = K >> 5;

    float4 ar[4], br[4];
#pragma unroll
    for (int i = 0; i < 4; i++) {
        ar[i] = *(const float4*)(Ap + 4 * i);
        br[i] = *(const float4*)(Bp + 4 * i);
    }

    for (int kc = 0; kc < NC; kc++) {
        const int s = kc & 1;
        uint32_t* A1 = su + s * STGU;
        uint32_t* A2 = A1 + ARRU;
        uint32_t* B1 = A2 + ARRU;
        uint32_t* B2 = B1 + ARRU;

        {
            uint4 bg, rs;
            split_pair(ar[0].x, ar[0].y, bg.x, rs.x);
            split_pair(ar[0].z, ar[0].w, bg.y, rs.y);
            split_pair(ar[1].x, ar[1].y, bg.z, rs.z);
            split_pair(ar[1].z, ar[1].w, bg.w, rs.w);
            *(uint4*)(A1 + sa) = bg; *(uint4*)(A2 + sa) = rs;
            split_pair(ar[2].x, ar[2].y, bg.x, rs.x);
            split_pair(ar[2].z, ar[2].w, bg.y, rs.y);
            split_pair(ar[3].x, ar[3].y, bg.z, rs.z);
            split_pair(ar[3].z, ar[3].w, bg.w, rs.w);
            *(uint4*)(A1 + sa + 4) = bg; *(uint4*)(A2 + sa + 4) = rs;

            split_pair(br[0].x, br[0].y, bg.x, rs.x);
            split_pair(br[0].z, br[0].w, bg.y, rs.y);
            split_pair(br[1].x, br[1].y, bg.z, rs.z);
            split_pair(br[1].z, br[1].w, bg.w, rs.w);
            *(uint4*)(B1 + sa) = bg; *(uint4*)(B2 + sa) = rs;
            split_pair(br[2].x, br[2].y, bg.x, rs.x);
            split_pair(br[2].z, br[2].w, bg.y, rs.y);
            split_pair(br[3].x, br[3].y, bg.z, rs.z);
            split_pair(br[3].z, br[3].w, bg.w, rs.w);
            *(uint4*)(B1 + sa + 4) = bg; *(uint4*)(B2 + sa + 4) = rs;
        }
        __syncthreads();

        if (kc + 1 < NC) {
            const int K0 = (kc + 1) << 5;
#pragma unroll
            for (int i = 0; i < 4; i++) {
                ar[i] = *(const float4*)(Ap + K0 + 4 * i);
                br[i] = *(const float4*)(Bp + K0 + 4 * i);
            }
        }

        BF16_CHUNK_COMPUTE(A1, A2, B1, B2);
        __syncthreads();
    }

    BF16_EPILOGUE();
}

// ---------------- K3: A pre-split (g_h1f/g_h2f), B fp32 split in loader ----------------
__global__ void __launch_bounds__(256, 2) bf16_gemm_preA_kernel(
    const uint32_t* __restrict__ A1g, const uint32_t* __restrict__ A2g,
    const float* __restrict__ Bm,
    const float* __restrict__ b1, const float* __restrict__ b2,
    float* __restrict__ C, int M, int N, int K)
{
    extern __shared__ uint32_t su[];
    const int tid = threadIdx.x;
    const int m0 = blockIdx.y << 7;
    const int n0 = blockIdx.x << 7;
    const int lane = tid & 31, wid = tid >> 5;
    const int gid = lane >> 2, tig = lane & 3;
    const int wm = wid >> 1, wn = wid & 1;

    const int lrow = tid >> 1;
    const int lko  = (tid & 1) << 4;       // float offset
    const int lkp  = lko >> 1;             // pair offset (0 or 8)
    const int sa   = lrow * PADB + lkp;
    const int KP   = K >> 1;               // pairs per row

    const uint32_t* A1p = A1g + (size_t)(m0 + lrow) * KP + lkp;
    const uint32_t* A2p = A2g + (size_t)(m0 + lrow) * KP + lkp;
    const float*    Bp  = Bm + (size_t)(n0 + lrow) * K + lko;

    float acc[2][8][4];
#pragma unroll
    for (int mt = 0; mt < 2; mt++)
#pragma unroll
        for (int nt = 0; nt < 8; nt++)
#pragma unroll
            for (int i = 0; i < 4; i++) acc[mt][nt][i] = 0.0f;

    const int NC = K >> 5;

    uint4 a1r0 = *(const uint4*)(A1p);
    uint4 a1r1 = *(const uint4*)(A1p + 4);
    uint4 a2r0 = *(const uint4*)(A2p);
    uint4 a2r1 = *(const uint4*)(A2p + 4);
    float4 br[4];
#pragma unroll
    for (int i = 0; i < 4; i++) br[i] = *(const float4*)(Bp + 4 * i);

    for (int kc = 0; kc < NC; kc++) {
        const int s = kc & 1;
        uint32_t* A1 = su + s * STGU;
        uint32_t* A2 = A1 + ARRU;
        uint32_t* B1 = A2 + ARRU;
        uint32_t* B2 = B1 + ARRU;

        {
            *(uint4*)(A1 + sa)     = a1r0;
            *(uint4*)(A1 + sa + 4) = a1r1;
            *(uint4*)(A2 + sa)     = a2r0;
            *(uint4*)(A2 + sa + 4) = a2r1;
            uint4 bg, rs;
            split_pair(br[0].x, br[0].y, bg.x, rs.x);
            split_pair(br[0].z, br[0].w, bg.y, rs.y);
            split_pair(br[1].x, br[1].y, bg.z, rs.z);
            split_pair(br[1].z, br[1].w, bg.w, rs.w);
            *(uint4*)(B1 + sa) = bg; *(uint4*)(B2 + sa) = rs;
            split_pair(br[2].x, br[2].y, bg.x, rs.x);
            split_pair(br[2].z, br[2].w, bg.y, rs.y);
            split_pair(br[3].x, br[3].y, bg.z, rs.z);
            split_pair(br[3].z, br[3].w, bg.w, rs.w);
            *(uint4*)(B1 + sa + 4) = bg; *(uint4*)(B2 + sa + 4) = rs;
        }
        __syncthreads();

        if (kc + 1 < NC) {
            const int P0 = (kc + 1) << 4;       // pair offset of next chunk
            a1r0 = *(const uint4*)(A1p + P0);
            a1r1 = *(const uint4*)(A1p + P0 + 4);
            a2r0 = *(const uint4*)(A2p + P0);
            a2r1 = *(const uint4*)(A2p + P0 + 4);
            const int K0 = (kc + 1) << 5;
#pragma unroll
            for (int i = 0; i < 4; i++) br[i] = *(const float4*)(Bp + K0 + 4 * i);
        }

        BF16_CHUNK_COMPUTE(A1, A2, B1, B2);
        __syncthreads();
    }

    BF16_EPILOGUE();
}

// ---------------- init ----------------
__global__ void zero_cnt_kernel() {
    if (threadIdx.x < NG) g_cnt[threadIdx.x] = 0;
}

// ---------------- K2: persistent recurrence (R15 core; full-T pre-split h, no fp32 h store) ----
#define REC_SMEM_BYTES ((2 * 64 * KS32 + 2 * 16 * KS32) * 4)   // 166400

__global__ void __launch_bounds__(256) rnn_rec_kernel(const float* __restrict__ w_hh)
{
    extern __shared__ uint32_t su[];
    uint32_t* W1 = su;                    // [64][260] bf16x2 pairs
    uint32_t* W2 = W1 + 64 * KS32;
    uint32_t* H1 = W2 + 64 * KS32;        // [16][260]
    uint32_t* H2 = H1 + 16 * KS32;

    const int tid = threadIdx.x;
    const int g = blockIdx.x >> 3;
    const int s = blockIdx.x & 7;
    const int n0 = s * NS;
    const int b0 = g * BT;

    // split W slice once
    for (int idx = tid; idx < 64 * 256; idx += 256) {
        const int n = idx >> 8, kp = idx & 255;
        const float f0 = w_hh[(size_t)(n0 + n) * H_ + 2 * kp];
        const float f1 = w_hh[(size_t)(n0 + n) * H_ + 2 * kp + 1];
        split_pair(f0, f1, W1[n * KS32 + kp], W2[n * KS32 + kp]);
    }
    for (int i = tid; i < 2 * 16 * KS32; i += 256) H1[i] = 0u;

    const int wid = tid >> 5, lane = tid & 31;
    const int gid = lane >> 2, tig = lane & 3;

    const uint32_t* h1a = H1 + gid * KS32;
    const uint32_t* h1b = H1 + (gid + 8) * KS32;
    const uint32_t* h2a = H2 + gid * KS32;
    const uint32_t* h2b = H2 + (gid + 8) * KS32;
    const uint32_t* w1p = W1 + (wid * 8 + gid) * KS32;
    const uint32_t* w2p = W2 + (wid * 8 + gid) * KS32;

    const uint32_t H1u = smem_u32(H1);
    const uint32_t H2u = smem_u32(H2);

    const size_t ob1 = ((size_t)(b0 + gid)) * H_ + n0 + wid * 8 + 2 * tig;
    const size_t ob2 = ob1 + (size_t)8 * H_;
    const int    kp1 = (b0 + gid) * 256 + (n0 >> 1) + wid * 4 + tig;
    const int    kp2 = kp1 + 8 * 256;

    const int* cntp = &g_cnt[g];

    __syncthreads();

    for (int t = 0; t < T_; t++) {
        const size_t tb = (size_t)t * B_ * H_;
        const float2 xv1 = __ldcs((const float2*)(g_xp + tb + ob1));
        const float2 xv2 = __ldcs((const float2*)(g_xp + tb + ob2));

        // --- acquire h_{t-1} (all threads) + direct cp.async of pre-split h ---
        if (t > 0) {
            unsigned int v;
            do {
                asm volatile("ld.acquire.gpu.global.b32 %0, [%1];" : "=r"(v) : "l"(cntp));
            } while (v < (unsigned int)(NSL * t));
            const uint32_t* s1 = g_h1f + (size_t)(t - 1) * B_ * 256;
            const uint32_t* s2 = g_h2f + (size_t)(t - 1) * B_ * 256;
#pragma unroll
            for (int j = 0; j < 4; j++) {
                const int c = tid + (j << 8);
                const int row = c >> 6, q = c & 63;
                const uint32_t dof = (uint32_t)(row * KS32 + q * 4) * 4;
                const size_t   sof = (size_t)(b0 + row) * 256 + q * 4;
                cp_async16(H1u + dof, s1 + sof);
                cp_async16(H2u + dof, s2 + sof);
            }
            CP_COMMIT_WAIT();
        }
        __syncthreads();

        // --- compute: 32 k16-blocks x 3 bf16 mma ---
        float c[4] = {0.0f, 0.0f, 0.0f, 0.0f};
#pragma unroll 8
        for (int kb = 0; kb < 32; kb++) {
            const int off = kb * 8 + tig;
            uint32_t A1[4], A2[4], B1[2], B2[2];
            A1[0] = h1a[off];     A1[1] = h1b[off];
            A1[2] = h1a[off + 4]; A1[3] = h1b[off + 4];
            A2[0] = h2a[off];     A2[1] = h2b[off];
            A2[2] = h2a[off + 4]; A2[3] = h2b[off + 4];
            B1[0] = w1p[off];     B1[1] = w1p[off + 4];
            B2[0] = w2p[off];     B2[1] = w2p[off + 4];
            mma16n8k16_bf16(c, A1, B1);
            mma16n8k16_bf16(c, A2, B1);
            mma16n8k16_bf16(c, A1, B2);
        }

        // --- epilogue: tanh, publish pre-split bf16x2 only (K3 consumes these) ---
        {
            uint32_t* d1 = g_h1f + (size_t)t * B_ * 256;
            uint32_t* d2 = g_h2f + (size_t)t * B_ * 256;
            float2 o1, o2;
            o1.x = tanhf(c[0] + xv1.x);
            o1.y = tanhf(c[1] + xv1.y);
            o2.x = tanhf(c[2] + xv2.x);
            o2.y = tanhf(c[3] + xv2.y);
            split_pair(o1.x, o1.y, d1[kp1], d2[kp1]);
            split_pair(o2.x, o2.y, d1[kp2], d2[kp2]);
        }
        __syncthreads();

        // --- release slice s of step t ---
        if (tid == 0) {
            asm volatile("red.release.gpu.global.add.u32 [%0], %1;"
                         :: "l"(cntp), "r"(1u) : "memory");
        }
    }
}

// ---------------- launch ----------------
extern "C" void kernel_launch(void* const* d_in, const int* in_sizes, int n_in,
                              void* d_out, int out_size)
{
    const float* x    = (const float*)d_in[0];
    const float* w_ih = (const float*)d_in[1];
    const float* w_hh = (const float*)d_in[2];
    const float* b_ih = (const float*)d_in[3];
    const float* b_hh = (const float*)d_in[4];
    const float* w_fc = (const float*)d_in[5];
    const float* b_fc = (const float*)d_in[6];
    float* out = (float*)d_out;

    float* xp = nullptr;
    uint32_t* h1 = nullptr;
    uint32_t* h2 = nullptr;
    cudaGetSymbolAddress((void**)&xp, g_xp);
    cudaGetSymbolAddress((void**)&h1, g_h1f);
    cudaGetSymbolAddress((void**)&h2, g_h2f);

    cudaFuncSetAttribute(rnn_rec_kernel, cudaFuncAttributeMaxDynamicSharedMemorySize, REC_SMEM_BYTES);
    cudaFuncSetAttribute(bf16_gemm_f32_kernel, cudaFuncAttributeMaxDynamicSharedMemorySize, GEMM_SMEM_BYTES);
    cudaFuncSetAttribute(bf16_gemm_preA_kernel, cudaFuncAttributeMaxDynamicSharedMemorySize, GEMM_SMEM_BYTES);

    const int M = T_ * B_;

    zero_cnt_kernel<<<1, 32>>>();

    // K1: xp = x @ w_ih^T + (b_ih + b_hh)   (M=131072, N=512, K=256)
    bf16_gemm_f32_kernel<<<dim3(H_ / 128, M / 128), 256, GEMM_SMEM_BYTES>>>(
        x, w_ih, b_ih, b_hh, xp, M, H_, I_);

    // K2: recurrence (persistent, 128 CTAs)
    rnn_rec_kernel<<<NG * NSL, 256, REC_SMEM_BYTES>>>(w_hh);

    // K3: out = hs @ w_fc^T + b_fc          (M=131072, N=256, K=512) — A pre-split
    bf16_gemm_preA_kernel<<<dim3(I_ / 128, M / 128), 256, GEMM_SMEM_BYTES>>>(
        h1, h2, w_fc, b_fc, nullptr, out, M, I_, H_);
}